// round 1
// baseline (speedup 1.0000x reference)
#include <cuda_runtime.h>
#include <cstdint>
#include <cstddef>

#define BS 256
#define KDIM 1024
#define NDIM 1024
#define NSTATES 20
#define TN 128      // n-columns per block
#define RCH 16      // max rows (samples) per block chunk
#define KC 512      // k elements staged per chunk
#define NWARPS 8
#define NTHREADS 256

__device__ __forceinline__ unsigned long long mul2(unsigned long long a, unsigned long long b) {
    unsigned long long d;
    asm("mul.rn.f32x2 %0, %1, %2;" : "=l"(d) : "l"(a), "l"(b));
    return d;
}
__device__ __forceinline__ unsigned long long fma2(unsigned long long a, unsigned long long b, unsigned long long c) {
    unsigned long long d;
    asm("fma.rn.f32x2 %0, %1, %2, %3;" : "=l"(d) : "l"(a), "l"(b), "l"(c));
    return d;
}

// Block = (n-tile, state, row-chunk). Computes out[rows_of_state, n0:n0+128].
__global__ __launch_bounds__(NTHREADS, 2)
void masked_dense_kernel(const float* __restrict__ x,
                         const int* __restrict__ state,
                         const float* __restrict__ kern,
                         const float* __restrict__ masks,
                         float* __restrict__ out)
{
    // 64KB dynamic smem: x chunk duplicated into f32x2 pairs [RCH][KC];
    // reused after the mainloop as the 8-warp reduction buffer [8][RCH*TN].
    extern __shared__ unsigned long long xs2[];
    __shared__ int rowlist[RCH];
    __shared__ int warp_cnt[NWARPS];

    const int t = threadIdx.x;
    const int w = t >> 5;
    const int lane = t & 31;
    const int s = blockIdx.y;
    const int z = blockIdx.z;
    const int n0 = blockIdx.x * TN;

    // ---- build row list for this (state, chunk) via ballots ----
    const int my_state = state[t];               // NTHREADS == BS
    const bool match = (my_state == s);
    const unsigned bal = __ballot_sync(0xffffffffu, match);
    if (lane == 0) warp_cnt[w] = __popc(bal);
    __syncthreads();

    int total = 0, before = 0;
#pragma unroll
    for (int i = 0; i < NWARPS; i++) {
        const int c = warp_cnt[i];
        if (i < w) before += c;
        total += c;
    }
    const int zbase = z * RCH;
    if (total <= zbase) return;                  // empty chunk: whole block exits
    const int nrows = min(total - zbase, RCH);

    const int rank = before + __popc(bal & ((1u << lane) - 1u));
    if (match && rank >= zbase && rank < zbase + RCH)
        rowlist[rank - zbase] = t;
    __syncthreads();

    // ---- accumulators: 16 rows x 4 cols as f32x2 pairs ----
    unsigned long long acc0[RCH], acc1[RCH];
#pragma unroll
    for (int r = 0; r < RCH; r++) { acc0[r] = 0ull; acc1[r] = 0ull; }

    const int gc = n0 + 4 * lane;                // this lane's 4 global columns

    for (int kc = 0; kc < KDIM / KC; kc++) {
        if (kc > 0) __syncthreads();             // previous chunk fully consumed
        // stage x[rows][kc*KC : +KC], duplicated (v,v) for packed FMA
        {
            float2* xsf2 = (float2*)xs2;
            for (int e4 = t; e4 < RCH * (KC / 4); e4 += NTHREADS) {
                const int r = e4 >> 7;                       // KC/4 == 128
                const int k4 = (e4 & 127) * 4;
                float4 v;
                if (r < nrows)
                    v = *(const float4*)&x[(size_t)rowlist[r] * KDIM + kc * KC + k4];
                else
                    v = make_float4(0.f, 0.f, 0.f, 0.f);
                const int base = r * KC + k4;
                xsf2[base + 0] = make_float2(v.x, v.x);
                xsf2[base + 1] = make_float2(v.y, v.y);
                xsf2[base + 2] = make_float2(v.z, v.z);
                xsf2[base + 3] = make_float2(v.w, v.w);
            }
        }
        __syncthreads();

        // warp w handles k in [kbase, kbase+64); lane handles 4 cols
        const int kbase = kc * KC + w * (KC / NWARPS);
        const float* mp = masks + ((size_t)s * KDIM + kbase) * NDIM + gc;
        const float* kp = kern + (size_t)kbase * NDIM + gc;
        const unsigned long long* xrow = xs2 + w * (KC / NWARPS);

#pragma unroll 4
        for (int kk = 0; kk < KC / NWARPS; kk++) {
            const ulonglong2 mv = *(const ulonglong2*)(mp + (size_t)kk * NDIM);
            const ulonglong2 kv = *(const ulonglong2*)(kp + (size_t)kk * NDIM);
            const unsigned long long w0 = mul2(mv.x, kv.x);  // masked weight, cols 0-1
            const unsigned long long w1 = mul2(mv.y, kv.y);  // cols 2-3
#pragma unroll
            for (int r = 0; r < RCH; r++) {
                const unsigned long long xv = xrow[r * KC + kk];  // broadcast LDS
                acc0[r] = fma2(xv, w0, acc0[r]);
                acc1[r] = fma2(xv, w1, acc1[r]);
            }
        }
    }
    __syncthreads();   // all warps done reading xs2 before overlay

    // ---- cross-warp k-reduction via flat smem buffer [8][RCH*TN] ----
    {
        unsigned long long* myb = xs2 + (size_t)w * (RCH * TN / 2);
        for (int r = 0; r < nrows; r++) {
            const int idx = r * (TN / 2) + 2 * lane;
            myb[idx]     = acc0[r];
            myb[idx + 1] = acc1[r];
        }
    }
    __syncthreads();

    const float* redf = (const float*)xs2;
    for (int e = t; e < nrows * TN; e += NTHREADS) {
        float v = 0.f;
#pragma unroll
        for (int ww = 0; ww < NWARPS; ww++) v += redf[ww * (RCH * TN) + e];
        v = fmaxf(v, 0.f);                         // ReLU
        const int r = e >> 7;
        const int c = e & 127;
        out[(size_t)rowlist[r] * NDIM + n0 + c] = v;
    }
}

extern "C" void kernel_launch(void* const* d_in, const int* in_sizes, int n_in,
                              void* d_out, int out_size)
{
    // Identify inputs by element count (all distinct): x=262144, state=256,
    // kernel=1048576, masks=20971520.
    const float* x = nullptr;
    const int* state = nullptr;
    const float* kern = nullptr;
    const float* masks = nullptr;
    for (int i = 0; i < n_in; i++) {
        switch (in_sizes[i]) {
            case BS * KDIM:          x = (const float*)d_in[i]; break;
            case BS:                 state = (const int*)d_in[i]; break;
            case KDIM * NDIM:        kern = (const float*)d_in[i]; break;
            case NSTATES * KDIM * NDIM: masks = (const float*)d_in[i]; break;
            default: break;
        }
    }
    float* out = (float*)d_out;

    const int smem_bytes = RCH * KC * (int)sizeof(unsigned long long);  // 64 KB
    static bool attr_set = false;
    if (!attr_set) {
        cudaFuncSetAttribute(masked_dense_kernel,
                             cudaFuncAttributeMaxDynamicSharedMemorySize, smem_bytes);
        attr_set = true;
    }

    dim3 grid(NDIM / TN, NSTATES, BS / RCH);   // (8, 20, 16)
    masked_dense_kernel<<<grid, NTHREADS, smem_bytes>>>(x, state, kern, masks, out);
}

// round 2
// speedup vs baseline: 1.2450x; 1.2450x over previous
#include <cuda_runtime.h>
#include <cstdint>
#include <cstddef>

#define BS 256
#define KDIM 1024
#define NDIM 1024
#define NSTATES 20
#define TN 64       // n-columns per block (2 per lane)
#define RCH 16      // max rows (samples) per block chunk
#define KC 512      // k elements staged per chunk
#define KSL (KC / NWARPS)   // 64 k per warp per chunk
#define NWARPS 8
#define NTHREADS 256

__device__ __forceinline__ unsigned long long mul2(unsigned long long a, unsigned long long b) {
    unsigned long long d;
    asm("mul.rn.f32x2 %0, %1, %2;" : "=l"(d) : "l"(a), "l"(b));
    return d;
}
__device__ __forceinline__ unsigned long long fma2(unsigned long long a, unsigned long long b, unsigned long long c) {
    unsigned long long d;
    asm("fma.rn.f32x2 %0, %1, %2, %3;" : "=l"(d) : "l"(a), "l"(b), "l"(c));
    return d;
}

// Block = (n-tile, state, row-chunk). Computes out[rows_of_state, n0:n0+64].
__global__ __launch_bounds__(NTHREADS, 2)
void masked_dense_kernel(const float* __restrict__ x,
                         const int* __restrict__ state,
                         const float* __restrict__ kern,
                         const float* __restrict__ masks,
                         float* __restrict__ out)
{
    // 64KB dynamic smem: x chunk duplicated into f32x2 pairs [RCH][KC];
    // reused after the mainloop as the 8-warp reduction buffer [8][RCH*TN] floats.
    extern __shared__ unsigned long long xs2[];
    __shared__ int rowlist[RCH];
    __shared__ int warp_cnt[NWARPS];

    const int t = threadIdx.x;
    const int w = t >> 5;
    const int lane = t & 31;
    const int s = blockIdx.y;
    const int z = blockIdx.z;
    const int n0 = blockIdx.x * TN;

    // ---- build row list for this (state, chunk) via ballots ----
    const int my_state = state[t];               // NTHREADS == BS
    const bool match = (my_state == s);
    const unsigned bal = __ballot_sync(0xffffffffu, match);
    if (lane == 0) warp_cnt[w] = __popc(bal);
    __syncthreads();

    int total = 0, before = 0;
#pragma unroll
    for (int i = 0; i < NWARPS; i++) {
        const int c = warp_cnt[i];
        if (i < w) before += c;
        total += c;
    }
    const int zbase = z * RCH;
    if (total <= zbase) return;                  // empty chunk: whole block exits
    const int nrows = min(total - zbase, RCH);

    const int rank = before + __popc(bal & ((1u << lane) - 1u));
    if (match && rank >= zbase && rank < zbase + RCH)
        rowlist[rank - zbase] = t;
    __syncthreads();

    // ---- accumulators: 16 rows x 2 cols (one f32x2 pair per row) ----
    unsigned long long acc[RCH];
#pragma unroll
    for (int r = 0; r < RCH; r++) acc[r] = 0ull;

    const int gc = n0 + 2 * lane;                // this lane's 2 global columns

    for (int kc = 0; kc < KDIM / KC; kc++) {
        if (kc > 0) __syncthreads();             // previous chunk fully consumed
        // stage x[rows][kc*KC : +KC], duplicated (v,v) for packed FMA
        {
            float4* xsf4 = (float4*)xs2;         // two duplicated pairs per float4
            for (int e4 = t; e4 < RCH * (KC / 4); e4 += NTHREADS) {
                const int r = e4 >> 7;                       // KC/4 == 128
                const int k4 = (e4 & 127) * 4;
                float4 v;
                if (r < nrows)
                    v = *(const float4*)&x[(size_t)rowlist[r] * KDIM + kc * KC + k4];
                else
                    v = make_float4(0.f, 0.f, 0.f, 0.f);
                const int base = (r * KC + k4) >> 1;         // float4 index
                xsf4[base + 0] = make_float4(v.x, v.x, v.y, v.y);
                xsf4[base + 1] = make_float4(v.z, v.z, v.w, v.w);
            }
        }
        __syncthreads();

        // warp w handles k in [kbase, kbase+KSL); lane handles 2 cols
        const int kbase = kc * KC + w * KSL;
        const float* mp = masks + ((size_t)s * KDIM + kbase) * NDIM + gc;
        const float* kp = kern + (size_t)kbase * NDIM + gc;
        const unsigned long long* xrow = xs2 + w * KSL;

        // double-buffered groups of 4 k-rows: 8 LDG.64 in flight per warp
        unsigned long long mbuf[2][4], kbuf[2][4];
#pragma unroll
        for (int j = 0; j < 4; j++) {
            mbuf[0][j] = *(const unsigned long long*)(mp + (size_t)j * NDIM);
            kbuf[0][j] = *(const unsigned long long*)(kp + (size_t)j * NDIM);
        }
#pragma unroll
        for (int g = 0; g < KSL / 4; g++) {
            const int cur = g & 1, nxt = cur ^ 1;
            if (g + 1 < KSL / 4) {
#pragma unroll
                for (int j = 0; j < 4; j++) {
                    const size_t off = (size_t)((g + 1) * 4 + j) * NDIM;
                    mbuf[nxt][j] = *(const unsigned long long*)(mp + off);
                    kbuf[nxt][j] = *(const unsigned long long*)(kp + off);
                }
            }
#pragma unroll
            for (int j = 0; j < 4; j++) {
                const unsigned long long w0 = mul2(mbuf[cur][j], kbuf[cur][j]);
                const unsigned long long* xk = xrow + (g * 4 + j);
#pragma unroll
                for (int r = 0; r < RCH; r++)
                    acc[r] = fma2(xk[r * KC], w0, acc[r]);   // broadcast LDS.64
            }
        }
    }
    __syncthreads();   // all warps done reading xs2 before overlay

    // ---- cross-warp k-reduction via flat smem buffer [8][RCH*TN] floats ----
    {
        unsigned long long* myb = xs2 + (size_t)w * (RCH * TN / 2);
#pragma unroll
        for (int r = 0; r < RCH; r++)
            myb[r * (TN / 2) + lane] = acc[r];
    }
    __syncthreads();

    const float* redf = (const float*)xs2;
    for (int e = t; e < nrows * TN; e += NTHREADS) {
        float v = 0.f;
#pragma unroll
        for (int ww = 0; ww < NWARPS; ww++) v += redf[ww * (RCH * TN) + e];
        v = fmaxf(v, 0.f);                         // ReLU
        const int r = e >> 6;                      // TN == 64
        const int c = e & 63;
        out[(size_t)rowlist[r] * NDIM + n0 + c] = v;
    }
}

extern "C" void kernel_launch(void* const* d_in, const int* in_sizes, int n_in,
                              void* d_out, int out_size)
{
    // Identify inputs by element count (all distinct): x=262144, state=256,
    // kernel=1048576, masks=20971520.
    const float* x = nullptr;
    const int* state = nullptr;
    const float* kern = nullptr;
    const float* masks = nullptr;
    for (int i = 0; i < n_in; i++) {
        switch (in_sizes[i]) {
            case BS * KDIM:          x = (const float*)d_in[i]; break;
            case BS:                 state = (const int*)d_in[i]; break;
            case KDIM * NDIM:        kern = (const float*)d_in[i]; break;
            case NSTATES * KDIM * NDIM: masks = (const float*)d_in[i]; break;
            default: break;
        }
    }
    float* out = (float*)d_out;

    const int smem_bytes = RCH * KC * (int)sizeof(unsigned long long);  // 64 KB
    static bool attr_set = false;
    if (!attr_set) {
        cudaFuncSetAttribute(masked_dense_kernel,
                             cudaFuncAttributeMaxDynamicSharedMemorySize, smem_bytes);
        attr_set = true;
    }

    dim3 grid(NDIM / TN, NSTATES, BS / RCH);   // (16, 20, 16)
    masked_dense_kernel<<<grid, NTHREADS, smem_bytes>>>(x, state, kern, masks, out);
}